// round 6
// baseline (speedup 1.0000x reference)
#include <cuda_runtime.h>
#include <cstdint>
#include <cstddef>

// ---------------------------------------------------------------------------
// MSReversibleRefine: B=4, DIM=64, HP=32, NHEAD=8, WS=16, H=W=128
//   d_in: 0 reused_attn (256,8,256,256) | 1 refined_lms (4,64,128,128)
//         2 hp_in (4,32,128,128) | 3 ra_w1 (8,8,1,3) | 4 ra_w2 (8,8,1,1)
//         5 ra_b2 (8) | 6 dw_w (64,1,3,3) | 7 dw_b (64) | 8 pw_w (64,64,1,1)
//         9 pw_b (64) | 10 fuse_w (64,96,3,3) | 11 fuse_b (64)
//   d_out: attn (134217728 f32) ++ out (4194304 f32)
// ---------------------------------------------------------------------------
#define ATTN_ELEMS 134217728LL
#define FULLM 0xffffffffu

typedef unsigned long long ull;

// f32x2 packed helpers (SASS FFMA2 — only reachable via PTX)
__device__ __forceinline__ ull pk2(float lo, float hi) {
    ull r; asm("mov.b64 %0, {%1, %2};" : "=l"(r) : "f"(lo), "f"(hi)); return r;
}
__device__ __forceinline__ void upk2(float& lo, float& hi, ull v) {
    asm("mov.b64 {%0, %1}, %2;" : "=f"(lo), "=f"(hi) : "l"(v));
}
__device__ __forceinline__ ull fma2(ull a, ull b, ull c) {
    ull d; asm("fma.rn.f32x2 %0, %1, %2, %3;" : "=l"(d) : "l"(a), "l"(b), "l"(c)); return d;
}

// scratch (static device globals: the sanctioned no-alloc workaround)
__device__ __align__(128) float g_refl[4 * 64 * 128 * 128]; // reflashed
__device__ __align__(128) float g_res [4 * 64 * 128 * 128]; // pw + reflashed
__device__ __align__(128) float g_fw  [96 * 9 * 64];        // fuse w: [c][tap][o]
__device__ __align__(128) ull   g_effp[200];                // [h][24 coeff-pairs + bias-pair]

// ---------------------------------------------------------------------------
// prep: eff[h][ci][dx] = sum_co w2[h,co]*w1[co,ci,dx] packed (e,e);
//       transpose fuse weights to [c][tap][o]
// ---------------------------------------------------------------------------
__global__ void prep_kernel(const float* __restrict__ w1, const float* __restrict__ w2,
                            const float* __restrict__ b2, const float* __restrict__ fw)
{
    int t = blockIdx.x * 256 + threadIdx.x;
    if (t < 200) {
        int h = t / 25, k = t % 25;
        float s;
        if (k < 24) {
            int ci = k / 3, dx = k % 3;
            s = 0.f;
            #pragma unroll
            for (int co = 0; co < 8; co++)
                s += w2[h * 8 + co] * w1[(co * 8 + ci) * 3 + dx];
        } else {
            s = b2[h];
        }
        g_effp[h * 25 + k] = pk2(s, s);
    }
    if (t < 96 * 9 * 64) {
        int o = t & 63;
        int r = t >> 6;
        int tap = r % 9;
        int c = r / 9;
        g_fw[t] = fw[(o * 96 + c) * 9 + tap];
    }
}

// ---------------------------------------------------------------------------
// attn kernel: one block per window (256 blocks), warp = head.
// eff-conv (8x8x3 stencil, packed f32x2) -> relu -> warp softmax -> STG attn,
// plus fused einsum (acc[d][n] += attn[m,n]*x[h,d,m]) in packed registers.
// ---------------------------------------------------------------------------
__global__ __launch_bounds__(256, 2)
void attn_kernel(const float* __restrict__ reused,
                 const float* __restrict__ refined,
                 float* __restrict__ attn_out)
{
    extern __shared__ float sm[];
    float* xw  = sm;                            // 64*256 window pixels [ch][m]
    float* buf = sm + 64 * 256;                 // 2 * 8 * 256 row double buffer
    ull*   effp = (ull*)(sm + 64 * 256 + 4096); // 200 pairs

    const int bw   = blockIdx.x;
    const int tid  = threadIdx.x;
    const int h    = tid >> 5;
    const int lane = tid & 31;

    const int b  = bw >> 6;
    const int g1 = (bw >> 3) & 7;
    const int g2 = bw & 7;

    for (int i = tid; i < 200; i += 256) effp[i] = g_effp[i];

    // load window pixels: xw[ch*256 + m] = refined[b, ch, (m>>4)*8+g1, (m&15)*8+g2]
    {
        const float* rbase = refined + (size_t)b * 64 * 16384;
        for (int i = tid; i < 16384; i += 256) {
            int ch = i >> 8, m = i & 255;
            int y = ((m >> 4) << 3) + g1;
            int x = ((m & 15) << 3) + g2;
            xw[i] = rbase[ch * 16384 + y * 128 + x];
        }
    }

    ull accp[8][4];
    #pragma unroll
    for (int d = 0; d < 8; d++)
        #pragma unroll
        for (int j = 0; j < 4; j++) accp[d][j] = 0ull;

    const size_t rowbase = (size_t)(bw * 8 + h) * 65536; // + m*256 per row

    const int c0w = lane,      s0w = c0w ^ ((c0w >> 3) & 7);
    const int c1w = 32 + lane, s1w = c1w ^ ((c1w >> 3) & 7);

    // preload row m=0 (warp h loads channel h)
    {
        const ulonglong2* rl = (const ulonglong2*)(reused + rowbase);
        ulonglong2 la = __ldg(rl + lane);
        ulonglong2 lb = __ldg(rl + 32 + lane);
        ulonglong2* bp = (ulonglong2*)(buf + h * 256);
        bp[s0w] = la;
        bp[s1w] = lb;
    }
    __syncthreads();

    const ull biasp = effp[h * 25 + 24];
    const int cA = 2 * lane;
    const int cB = cA + 1;
    const int sA = cA ^ ((cA >> 3) & 7);
    const int sB = cB ^ ((cB >> 3) & 7);

    #pragma unroll 1
    for (int m = 0; m < 256; m++) {
        const int ph = m & 1;
        const bool pre = (m + 1 < 256);
        ulonglong2 la, lb;
        if (pre) {
            const ulonglong2* rl = (const ulonglong2*)(reused + rowbase + (size_t)(m + 1) * 256);
            la = __ldg(rl + lane);
            lb = __ldg(rl + 32 + lane);
        }

        // effective 8x8x3 stencil in f32x2 pairs
        ull A0 = biasp, A1 = biasp, A2 = biasp, A3 = biasp;
        const ulonglong2* rp = (const ulonglong2*)(buf + ph * 2048);
        #pragma unroll
        for (int c = 0; c < 8; c++) {
            ulonglong2 ua = rp[c * 64 + sA];   // (v0,v1) (v2,v3)
            ulonglong2 ub = rp[c * 64 + sB];   // (v4,v5) (v6,v7)
            float v0, v1, v2, v3, v4, v5, v6, v7;
            upk2(v0, v1, ua.x); upk2(v2, v3, ua.y);
            upk2(v4, v5, ub.x); upk2(v6, v7, ub.y);
            float lh = __shfl_up_sync(FULLM, v7, 1);
            float rh = __shfl_down_sync(FULLM, v0, 1);
            if (lane == 0)  lh = 0.f;
            if (lane == 31) rh = 0.f;
            ull S0 = pk2(lh, v0);
            ull S1 = pk2(v1, v2);
            ull S2 = pk2(v3, v4);
            ull S3 = pk2(v5, v6);
            ull S4 = pk2(v7, rh);
            ull E0 = effp[h * 25 + c * 3 + 0];
            ull E1 = effp[h * 25 + c * 3 + 1];
            ull E2 = effp[h * 25 + c * 3 + 2];
            A0 = fma2(E0, S0, A0); A0 = fma2(E1, ua.x, A0); A0 = fma2(E2, S1, A0);
            A1 = fma2(E0, S1, A1); A1 = fma2(E1, ua.y, A1); A1 = fma2(E2, S2, A1);
            A2 = fma2(E0, S2, A2); A2 = fma2(E1, ub.x, A2); A2 = fma2(E2, S3, A2);
            A3 = fma2(E0, S3, A3); A3 = fma2(E1, ub.y, A3); A3 = fma2(E2, S4, A3);
        }

        // unpack, relu + warp softmax over 256 (8 per lane)
        float a[8];
        upk2(a[0], a[1], A0); upk2(a[2], a[3], A1);
        upk2(a[4], a[5], A2); upk2(a[6], a[7], A3);

        float mx = 0.f;
        #pragma unroll
        for (int i = 0; i < 8; i++) { a[i] = fmaxf(a[i], 0.f); mx = fmaxf(mx, a[i]); }
        #pragma unroll
        for (int o = 16; o; o >>= 1) mx = fmaxf(mx, __shfl_xor_sync(FULLM, mx, o));
        float sum = 0.f;
        #pragma unroll
        for (int i = 0; i < 8; i++) { a[i] = __expf(a[i] - mx); sum += a[i]; }
        #pragma unroll
        for (int o = 16; o; o >>= 1) sum += __shfl_xor_sync(FULLM, sum, o);
        float inv = __fdividef(1.f, sum);
        #pragma unroll
        for (int i = 0; i < 8; i++) a[i] *= inv;

        // store attn row (two STG.128 per lane, warp-coalesced)
        {
            float4* op = (float4*)(attn_out + rowbase + (size_t)m * 256);
            op[2 * lane]     = make_float4(a[0], a[1], a[2], a[3]);
            op[2 * lane + 1] = make_float4(a[4], a[5], a[6], a[7]);
        }

        // fused einsum accumulate (packed): accp[d][j] += ap[j] * (xv,xv)
        {
            ull ap0 = pk2(a[0], a[1]);
            ull ap1 = pk2(a[2], a[3]);
            ull ap2 = pk2(a[4], a[5]);
            ull ap3 = pk2(a[6], a[7]);
            const float* xcol = xw + (h * 8) * 256 + m;
            #pragma unroll
            for (int d = 0; d < 8; d++) {
                float xv = xcol[d * 256]; // broadcast LDS
                ull xp = pk2(xv, xv);
                accp[d][0] = fma2(ap0, xp, accp[d][0]);
                accp[d][1] = fma2(ap1, xp, accp[d][1]);
                accp[d][2] = fma2(ap2, xp, accp[d][2]);
                accp[d][3] = fma2(ap3, xp, accp[d][3]);
            }
        }

        // stage prefetched row
        if (pre) {
            ulonglong2* bp = (ulonglong2*)(buf + (ph ^ 1) * 2048 + h * 256);
            bp[s0w] = la;
            bp[s1w] = lb;
        }
        __syncthreads();
    }

    // scatter reflashed: g_refl[b, h*8+d, (n>>4)*8+g1, (n&15)*8+g2]
    {
        float* gout = g_refl + ((size_t)b * 64 + h * 8) * 16384;
        #pragma unroll
        for (int d = 0; d < 8; d++) {
            #pragma unroll
            for (int j = 0; j < 4; j++) {
                float f0, f1;
                upk2(f0, f1, accp[d][j]);
                int n0 = lane * 8 + 2 * j;
                int y0 = ((n0 >> 4) << 3) + g1;
                int x0 = ((n0 & 15) << 3) + g2;
                gout[d * 16384 + y0 * 128 + x0] = f0;
                int n1 = n0 + 1;
                int y1 = ((n1 >> 4) << 3) + g1;
                int x1 = ((n1 & 15) << 3) + g2;
                gout[d * 16384 + y1 * 128 + x1] = f1;
            }
        }
    }
}

// ---------------------------------------------------------------------------
// merged depthwise 3x3 + relu + pointwise 64->64 + residual : g_refl -> g_res
// block = 16x16 pixel tile, dw result kept in packed registers.
// ---------------------------------------------------------------------------
__global__ __launch_bounds__(256, 2)
void dwpw_kernel(const float* __restrict__ dww, const float* __restrict__ dwb,
                 const float* __restrict__ pww, const float* __restrict__ pwb)
{
    __shared__ float tile[8 * 324];   // 8 ch x 18x18
    __shared__ float pwsh[4096];
    __shared__ float pwbsh[64];
    __shared__ float dwsh[576];
    __shared__ float dwbsh[64];

    int b   = blockIdx.z;
    int tyb = blockIdx.y * 16;
    int txb = blockIdx.x * 16;
    int tid = threadIdx.x;
    int tx  = tid & 15, ty = tid >> 4;

    for (int i = tid; i < 4096; i += 256) pwsh[i] = pww[i];
    for (int i = tid; i < 576;  i += 256) dwsh[i] = dww[i];
    if (tid < 64) { pwbsh[tid] = pwb[tid]; dwbsh[tid] = dwb[tid]; }

    ull dwp[32];

    for (int cc = 0; cc < 64; cc += 8) {
        __syncthreads();
        for (int i = tid; i < 8 * 324; i += 256) {
            int c = i / 324, r = i % 324;
            int iy = r / 18, ix = r % 18;
            int y = tyb + iy - 1, x = txb + ix - 1;
            float v = 0.f;
            if ((unsigned)y < 128u && (unsigned)x < 128u)
                v = g_refl[((size_t)b * 64 + cc + c) * 16384 + y * 128 + x];
            tile[i] = v;
        }
        __syncthreads();

        float sv[8];
        #pragma unroll
        for (int c = 0; c < 8; c++) {
            const float* w = dwsh + (cc + c) * 9;
            float s = dwbsh[cc + c];
            #pragma unroll
            for (int tap = 0; tap < 9; tap++) {
                int dy = tap / 3, dx = tap % 3;
                s = fmaf(w[tap], tile[c * 324 + (ty + dy) * 18 + (tx + dx)], s);
            }
            sv[c] = fmaxf(s, 0.f);
        }
        #pragma unroll
        for (int j = 0; j < 4; j++)
            dwp[(cc >> 1) + j] = pk2(sv[2 * j], sv[2 * j + 1]);
    }

    int y = tyb + ty, x = txb + tx;
    size_t pix = (size_t)y * 128 + x;
    const float* rin = g_refl + (size_t)b * 64 * 16384 + pix;
    float*       ro  = g_res  + (size_t)b * 64 * 16384 + pix;

    #pragma unroll 4
    for (int o = 0; o < 64; o++) {
        ull acc2 = 0ull;
        const ulonglong2* wr = (const ulonglong2*)(pwsh + o * 64);
        #pragma unroll
        for (int c4 = 0; c4 < 16; c4++) {
            ulonglong2 uw = wr[c4];
            acc2 = fma2(uw.x, dwp[2 * c4],     acc2);
            acc2 = fma2(uw.y, dwp[2 * c4 + 1], acc2);
        }
        float lo, hi;
        upk2(lo, hi, acc2);
        ro[o * 16384] = lo + hi + pwbsh[o] + rin[o * 16384];
    }
}

// ---------------------------------------------------------------------------
// fuse conv 3x3 (96 -> 64) + bias, then out = g_refl * conv  (packed f32x2)
// ---------------------------------------------------------------------------
__global__ __launch_bounds__(256, 2)
void fuse_kernel(const float* __restrict__ hp, const float* __restrict__ fb,
                 float* __restrict__ out)
{
    __shared__ float tile[8 * 324];   // 8 ch x 18x18
    __shared__ float wsh[8 * 9 * 64]; // 8 ch x 9 taps x 64 o

    int b   = blockIdx.z;
    int tyb = blockIdx.y * 16;
    int txb = blockIdx.x * 16;
    int tid = threadIdx.x;
    int tx  = tid & 15, ty = tid >> 4;

    ull accp[32];
    #pragma unroll
    for (int j = 0; j < 32; j++) accp[j] = 0ull;

    for (int cc = 0; cc < 96; cc += 8) {
        __syncthreads();
        for (int i = tid; i < 8 * 324; i += 256) {
            int c = i / 324, r = i % 324;
            int iy = r / 18, ix = r % 18;
            int y = tyb + iy - 1, x = txb + ix - 1;
            float v = 0.f;
            if ((unsigned)y < 128u && (unsigned)x < 128u) {
                int ch = cc + c;
                v = (ch < 64)
                    ? g_res[((size_t)b * 64 + ch) * 16384 + y * 128 + x]
                    : hp  [((size_t)b * 32 + (ch - 64)) * 16384 + y * 128 + x];
            }
            tile[i] = v;
        }
        for (int i = tid; i < 8 * 576; i += 256) wsh[i] = g_fw[cc * 576 + i];
        __syncthreads();

        #pragma unroll 1
        for (int c = 0; c < 8; c++) {
            #pragma unroll
            for (int tap = 0; tap < 9; tap++) {
                int dy = tap / 3, dx = tap % 3;
                float v = tile[c * 324 + (ty + dy) * 18 + (tx + dx)];
                ull vp = pk2(v, v);
                const ulonglong2* wp = (const ulonglong2*)(wsh + (c * 9 + tap) * 64);
                #pragma unroll
                for (int o4 = 0; o4 < 16; o4++) {
                    ulonglong2 uw = wp[o4]; // broadcast LDS.128
                    accp[2 * o4]     = fma2(uw.x, vp, accp[2 * o4]);
                    accp[2 * o4 + 1] = fma2(uw.y, vp, accp[2 * o4 + 1]);
                }
            }
        }
    }

    int y = tyb + ty, x = txb + tx;
    size_t pix = (size_t)y * 128 + x;
    #pragma unroll 4
    for (int j = 0; j < 32; j++) {
        float f0, f1;
        upk2(f0, f1, accp[j]);
        int o0 = 2 * j;
        size_t i0 = ((size_t)b * 64 + o0) * 16384 + pix;
        size_t i1 = i0 + 16384;
        out[i0] = g_refl[i0] * (f0 + fb[o0]);
        out[i1] = g_refl[i1] * (f1 + fb[o0 + 1]);
    }
}

// ---------------------------------------------------------------------------
extern "C" void kernel_launch(void* const* d_in, const int* in_sizes, int n_in,
                              void* d_out, int out_size)
{
    const float* reused  = (const float*)d_in[0];
    const float* refined = (const float*)d_in[1];
    const float* hp      = (const float*)d_in[2];
    const float* ra_w1   = (const float*)d_in[3];
    const float* ra_w2   = (const float*)d_in[4];
    const float* ra_b2   = (const float*)d_in[5];
    const float* dw_w    = (const float*)d_in[6];
    const float* dw_b    = (const float*)d_in[7];
    const float* pw_w    = (const float*)d_in[8];
    const float* pw_b    = (const float*)d_in[9];
    const float* fuse_w  = (const float*)d_in[10];
    const float* fuse_b  = (const float*)d_in[11];

    float* attn_out = (float*)d_out;
    float* out_out  = (float*)d_out + ATTN_ELEMS;

    // 1. weight prep
    prep_kernel<<<216, 256>>>(ra_w1, ra_w2, ra_b2, fuse_w);

    // 2. fused attn-conv + softmax + einsum
    const int smem = (64 * 256 + 2 * 2048) * (int)sizeof(float) + 200 * (int)sizeof(ull);
    cudaFuncSetAttribute(attn_kernel, cudaFuncAttributeMaxDynamicSharedMemorySize, smem);
    attn_kernel<<<256, 256, smem>>>(reused, refined, attn_out);

    // 3. depthwise + relu + pointwise + residual (merged)
    dwpw_kernel<<<dim3(8, 8, 4), 256>>>(dw_w, dw_b, pw_w, pw_b);

    // 4. fuse conv + gate
    fuse_kernel<<<dim3(8, 8, 4), 256>>>(hp, fuse_b, out_out);
}

// round 7
// speedup vs baseline: 1.0759x; 1.0759x over previous
#include <cuda_runtime.h>
#include <cstdint>
#include <cstddef>

// ---------------------------------------------------------------------------
// MSReversibleRefine: B=4, DIM=64, HP=32, NHEAD=8, WS=16, H=W=128
//   d_in: 0 reused_attn (256,8,256,256) | 1 refined_lms (4,64,128,128)
//         2 hp_in (4,32,128,128) | 3 ra_w1 (8,8,1,3) | 4 ra_w2 (8,8,1,1)
//         5 ra_b2 (8) | 6 dw_w (64,1,3,3) | 7 dw_b (64) | 8 pw_w (64,64,1,1)
//         9 pw_b (64) | 10 fuse_w (64,96,3,3) | 11 fuse_b (64)
//   d_out: attn (134217728 f32) ++ out (4194304 f32)
// ---------------------------------------------------------------------------
#define ATTN_ELEMS 134217728LL
#define FULLM 0xffffffffu

typedef unsigned long long ull;

// f32x2 packed helpers (SASS FFMA2 — only reachable via PTX)
__device__ __forceinline__ ull pk2(float lo, float hi) {
    ull r; asm("mov.b64 %0, {%1, %2};" : "=l"(r) : "f"(lo), "f"(hi)); return r;
}
__device__ __forceinline__ void upk2(float& lo, float& hi, ull v) {
    asm("mov.b64 {%0, %1}, %2;" : "=f"(lo), "=f"(hi) : "l"(v));
}
__device__ __forceinline__ ull fma2(ull a, ull b, ull c) {
    ull d; asm("fma.rn.f32x2 %0, %1, %2, %3;" : "=l"(d) : "l"(a), "l"(b), "l"(c)); return d;
}

// scratch (static device globals: the sanctioned no-alloc workaround)
__device__ __align__(128) float g_refl[4 * 64 * 128 * 128]; // reflashed
__device__ __align__(128) float g_res [4 * 64 * 128 * 128]; // pw + reflashed
__device__ __align__(128) float g_fw  [96 * 9 * 64];        // fuse w: [c][tap][o]
__device__ __align__(128) float g_eff [200];                // [h][24 coeffs + bias]

// ---------------------------------------------------------------------------
// prep: eff[h][ci][dx] = sum_co w2[h,co]*w1[co,ci,dx]; transpose fuse weights
// ---------------------------------------------------------------------------
__global__ void prep_kernel(const float* __restrict__ w1, const float* __restrict__ w2,
                            const float* __restrict__ b2, const float* __restrict__ fw)
{
    int t = blockIdx.x * 256 + threadIdx.x;
    if (t < 200) {
        int h = t / 25, k = t % 25;
        if (k < 24) {
            int ci = k / 3, dx = k % 3;
            float s = 0.f;
            #pragma unroll
            for (int co = 0; co < 8; co++)
                s += w2[h * 8 + co] * w1[(co * 8 + ci) * 3 + dx];
            g_eff[h * 25 + k] = s;
        } else {
            g_eff[h * 25 + 24] = b2[h];
        }
    }
    if (t < 96 * 9 * 64) {
        int o = t & 63;
        int r = t >> 6;
        int tap = r % 9;
        int c = r / 9;
        g_fw[t] = fw[(o * 96 + c) * 9 + tap];
    }
}

// ---------------------------------------------------------------------------
// attn kernel (scalar stencil — measured faster than the packed variant):
// one block per window (256 blocks), warp = head.
// eff-conv -> relu -> warp softmax -> STG attn, + fused einsum in registers.
// ---------------------------------------------------------------------------
__global__ __launch_bounds__(256, 2)
void attn_kernel(const float* __restrict__ reused,
                 const float* __restrict__ refined,
                 float* __restrict__ attn_out)
{
    extern __shared__ float sm[];
    float* xw  = sm;                       // 64*256 window pixels [ch][m]
    float* buf = sm + 64 * 256;            // 2 * 8 * 256 row double buffer
    float* eff = sm + 64 * 256 + 2 * 2048; // 200

    const int bw   = blockIdx.x;
    const int tid  = threadIdx.x;
    const int h    = tid >> 5;
    const int lane = tid & 31;

    const int b  = bw >> 6;
    const int g1 = (bw >> 3) & 7;
    const int g2 = bw & 7;

    for (int i = tid; i < 200; i += 256) eff[i] = g_eff[i];

    // load window pixels: xw[ch*256 + m] = refined[b, ch, (m>>4)*8+g1, (m&15)*8+g2]
    {
        const float* rbase = refined + (size_t)b * 64 * 16384;
        for (int i = tid; i < 16384; i += 256) {
            int ch = i >> 8, m = i & 255;
            int y = ((m >> 4) << 3) + g1;
            int x = ((m & 15) << 3) + g2;
            xw[i] = rbase[ch * 16384 + y * 128 + x];
        }
    }

    float acc[8][8];
    #pragma unroll
    for (int d = 0; d < 8; d++)
        #pragma unroll
        for (int i = 0; i < 8; i++) acc[d][i] = 0.f;

    const size_t rowbase = (size_t)(bw * 8 + h) * 65536; // + m*256 per row

    // preload row m=0 (warp h loads channel h)
    {
        const float4* rl = (const float4*)(reused + rowbase);
        float4 la = __ldg(rl + lane);
        float4 lb = __ldg(rl + 32 + lane);
        float4* bp = (float4*)(buf + h * 256);
        int c0 = lane,      s0 = c0 ^ ((c0 >> 3) & 7);
        int c1 = 32 + lane, s1 = c1 ^ ((c1 >> 3) & 7);
        bp[s0] = la;
        bp[s1] = lb;
    }
    __syncthreads();

    const float bias = eff[h * 25 + 24];
    const int cA = 2 * lane;
    const int cB = cA + 1;
    const int sA = cA ^ ((cA >> 3) & 7);
    const int sB = cB ^ ((cB >> 3) & 7);

    #pragma unroll 1
    for (int m = 0; m < 256; m++) {
        const int ph = m & 1;
        const bool pre = (m + 1 < 256);
        float4 la, lb;
        if (pre) {
            const float4* rl = (const float4*)(reused + rowbase + (size_t)(m + 1) * 256);
            la = __ldg(rl + lane);
            lb = __ldg(rl + 32 + lane);
        }

        // effective 8x8x3 stencil
        float a[8];
        #pragma unroll
        for (int i = 0; i < 8; i++) a[i] = bias;

        const float4* rp = (const float4*)(buf + ph * 2048);
        #pragma unroll
        for (int c = 0; c < 8; c++) {
            float4 va = rp[c * 64 + sA];
            float4 vb = rp[c * 64 + sB];
            float v[8] = {va.x, va.y, va.z, va.w, vb.x, vb.y, vb.z, vb.w};
            float lh = __shfl_up_sync(FULLM, v[7], 1);
            float rh = __shfl_down_sync(FULLM, v[0], 1);
            if (lane == 0)  lh = 0.f;
            if (lane == 31) rh = 0.f;
            float e0 = eff[h * 25 + c * 3 + 0];
            float e1 = eff[h * 25 + c * 3 + 1];
            float e2 = eff[h * 25 + c * 3 + 2];
            #pragma unroll
            for (int i = 0; i < 8; i++) {
                float L = (i == 0) ? lh : v[i - 1];
                float R = (i == 7) ? rh : v[i + 1];
                a[i] = fmaf(e0, L, a[i]);
                a[i] = fmaf(e1, v[i], a[i]);
                a[i] = fmaf(e2, R, a[i]);
            }
        }

        // relu + warp softmax over 256 (8 per lane)
        float mx = 0.f;
        #pragma unroll
        for (int i = 0; i < 8; i++) { a[i] = fmaxf(a[i], 0.f); mx = fmaxf(mx, a[i]); }
        #pragma unroll
        for (int o = 16; o; o >>= 1) mx = fmaxf(mx, __shfl_xor_sync(FULLM, mx, o));
        float sum = 0.f;
        #pragma unroll
        for (int i = 0; i < 8; i++) { a[i] = __expf(a[i] - mx); sum += a[i]; }
        #pragma unroll
        for (int o = 16; o; o >>= 1) sum += __shfl_xor_sync(FULLM, sum, o);
        float inv = __fdividef(1.f, sum);
        #pragma unroll
        for (int i = 0; i < 8; i++) a[i] *= inv;

        // store attn row (two STG.128 per lane, warp-coalesced)
        {
            float4* op = (float4*)(attn_out + rowbase + (size_t)m * 256);
            op[2 * lane]     = make_float4(a[0], a[1], a[2], a[3]);
            op[2 * lane + 1] = make_float4(a[4], a[5], a[6], a[7]);
        }

        // fused einsum accumulate: acc[d][i] += a[i] * x[h,d,m]
        {
            const float* xcol = xw + (h * 8) * 256 + m;
            #pragma unroll
            for (int d = 0; d < 8; d++) {
                float xv = xcol[d * 256]; // broadcast LDS
                #pragma unroll
                for (int i = 0; i < 8; i++) acc[d][i] = fmaf(a[i], xv, acc[d][i]);
            }
        }

        // stage prefetched row
        if (pre) {
            float4* bp = (float4*)(buf + (ph ^ 1) * 2048 + h * 256);
            int c0 = lane,      s0 = c0 ^ ((c0 >> 3) & 7);
            int c1 = 32 + lane, s1 = c1 ^ ((c1 >> 3) & 7);
            bp[s0] = la;
            bp[s1] = lb;
        }
        __syncthreads();
    }

    // scatter reflashed: g_refl[b, h*8+d, (n>>4)*8+g1, (n&15)*8+g2]
    {
        float* gout = g_refl + ((size_t)b * 64 + h * 8) * 16384;
        #pragma unroll
        for (int d = 0; d < 8; d++) {
            #pragma unroll
            for (int i = 0; i < 8; i++) {
                int n = lane * 8 + i;
                int y = ((n >> 4) << 3) + g1;
                int x = ((n & 15) << 3) + g2;
                gout[d * 16384 + y * 128 + x] = acc[d][i];
            }
        }
    }
}

// ---------------------------------------------------------------------------
// merged depthwise 3x3 + relu + pointwise 64->64 + residual : g_refl -> g_res
// ---------------------------------------------------------------------------
__global__ __launch_bounds__(256, 2)
void dwpw_kernel(const float* __restrict__ dww, const float* __restrict__ dwb,
                 const float* __restrict__ pww, const float* __restrict__ pwb)
{
    __shared__ float tile[8 * 324];   // 8 ch x 18x18
    __shared__ float pwsh[4096];
    __shared__ float pwbsh[64];
    __shared__ float dwsh[576];
    __shared__ float dwbsh[64];

    int b   = blockIdx.z;
    int tyb = blockIdx.y * 16;
    int txb = blockIdx.x * 16;
    int tid = threadIdx.x;
    int tx  = tid & 15, ty = tid >> 4;

    for (int i = tid; i < 4096; i += 256) pwsh[i] = pww[i];
    for (int i = tid; i < 576;  i += 256) dwsh[i] = dww[i];
    if (tid < 64) { pwbsh[tid] = pwb[tid]; dwbsh[tid] = dwb[tid]; }

    ull dwp[32];

    for (int cc = 0; cc < 64; cc += 8) {
        __syncthreads();
        for (int i = tid; i < 8 * 324; i += 256) {
            int c = i / 324, r = i % 324;
            int iy = r / 18, ix = r % 18;
            int y = tyb + iy - 1, x = txb + ix - 1;
            float v = 0.f;
            if ((unsigned)y < 128u && (unsigned)x < 128u)
                v = g_refl[((size_t)b * 64 + cc + c) * 16384 + y * 128 + x];
            tile[i] = v;
        }
        __syncthreads();

        float sv[8];
        #pragma unroll
        for (int c = 0; c < 8; c++) {
            const float* w = dwsh + (cc + c) * 9;
            float s = dwbsh[cc + c];
            #pragma unroll
            for (int tap = 0; tap < 9; tap++) {
                int dy = tap / 3, dx = tap % 3;
                s = fmaf(w[tap], tile[c * 324 + (ty + dy) * 18 + (tx + dx)], s);
            }
            sv[c] = fmaxf(s, 0.f);
        }
        #pragma unroll
        for (int j = 0; j < 4; j++)
            dwp[(cc >> 1) + j] = pk2(sv[2 * j], sv[2 * j + 1]);
    }

    int y = tyb + ty, x = txb + tx;
    size_t pix = (size_t)y * 128 + x;
    const float* rin = g_refl + (size_t)b * 64 * 16384 + pix;
    float*       ro  = g_res  + (size_t)b * 64 * 16384 + pix;

    #pragma unroll 4
    for (int o = 0; o < 64; o++) {
        ull acc2 = 0ull;
        const ulonglong2* wr = (const ulonglong2*)(pwsh + o * 64);
        #pragma unroll
        for (int c4 = 0; c4 < 16; c4++) {
            ulonglong2 uw = wr[c4];
            acc2 = fma2(uw.x, dwp[2 * c4],     acc2);
            acc2 = fma2(uw.y, dwp[2 * c4 + 1], acc2);
        }
        float lo, hi;
        upk2(lo, hi, acc2);
        ro[o * 16384] = lo + hi + pwbsh[o] + rin[o * 16384];
    }
}

// ---------------------------------------------------------------------------
// fuse conv 3x3 (96 -> 64) + bias, then out = g_refl * conv.
// Thread = (pixel, o-half): block = 16x8 pixel tile x 2 o-groups of 32.
// Per (c,tap) step/warp: 8 broadcast LDS.128 + 1 v-load vs 16 FFMA2 -> FFMA-bound.
// ---------------------------------------------------------------------------
__global__ __launch_bounds__(256, 4)
void fuse_kernel(const float* __restrict__ hp, const float* __restrict__ fb,
                 float* __restrict__ out)
{
    __shared__ float tile[8 * 180];   // 8 ch x 10x18 (16x8 tile + halo)
    __shared__ float wsh[8 * 9 * 64]; // 8 ch x 9 taps x 64 o

    const int b   = blockIdx.z;
    const int tyb = blockIdx.y * 8;
    const int txb = blockIdx.x * 16;
    const int tid = threadIdx.x;
    const int og  = tid >> 7;         // o-group: 0 or 1 (warp-uniform)
    const int p   = tid & 127;
    const int tx  = p & 15, ty = p >> 4;

    ull accp[16];
    #pragma unroll
    for (int j = 0; j < 16; j++) accp[j] = 0ull;

    for (int cc = 0; cc < 96; cc += 8) {
        __syncthreads();
        // stage 8-channel 10x18 input tile with zero-pad halo
        for (int i = tid; i < 8 * 180; i += 256) {
            int c = i / 180, r = i % 180;
            int iy = r / 18, ix = r % 18;
            int y = tyb + iy - 1, x = txb + ix - 1;
            float v = 0.f;
            if ((unsigned)y < 128u && (unsigned)x < 128u) {
                int ch = cc + c;
                v = (ch < 64)
                    ? g_res[((size_t)b * 64 + ch) * 16384 + y * 128 + x]
                    : hp  [((size_t)b * 32 + (ch - 64)) * 16384 + y * 128 + x];
            }
            tile[i] = v;
        }
        // stage weights (already o-contiguous)
        for (int i = tid; i < 8 * 576; i += 256) wsh[i] = g_fw[cc * 576 + i];
        __syncthreads();

        #pragma unroll 1
        for (int c = 0; c < 8; c++) {
            #pragma unroll
            for (int tap = 0; tap < 9; tap++) {
                int dy = tap / 3, dx = tap % 3;
                float v = tile[c * 180 + (ty + dy) * 18 + (tx + dx)];
                ull vp = pk2(v, v);
                const ulonglong2* wp = (const ulonglong2*)(wsh + (c * 9 + tap) * 64 + og * 32);
                #pragma unroll
                for (int j4 = 0; j4 < 8; j4++) {
                    ulonglong2 uw = wp[j4]; // broadcast LDS.128
                    accp[2 * j4]     = fma2(uw.x, vp, accp[2 * j4]);
                    accp[2 * j4 + 1] = fma2(uw.y, vp, accp[2 * j4 + 1]);
                }
            }
        }
    }

    const int y = tyb + ty, x = txb + tx;
    const size_t pix = (size_t)y * 128 + x;
    #pragma unroll 4
    for (int j = 0; j < 16; j++) {
        float f0, f1;
        upk2(f0, f1, accp[j]);
        int o0 = og * 32 + 2 * j;
        size_t i0 = ((size_t)b * 64 + o0) * 16384 + pix;
        size_t i1 = i0 + 16384;
        out[i0] = g_refl[i0] * (f0 + fb[o0]);
        out[i1] = g_refl[i1] * (f1 + fb[o0 + 1]);
    }
}

// ---------------------------------------------------------------------------
extern "C" void kernel_launch(void* const* d_in, const int* in_sizes, int n_in,
                              void* d_out, int out_size)
{
    const float* reused  = (const float*)d_in[0];
    const float* refined = (const float*)d_in[1];
    const float* hp      = (const float*)d_in[2];
    const float* ra_w1   = (const float*)d_in[3];
    const float* ra_w2   = (const float*)d_in[4];
    const float* ra_b2   = (const float*)d_in[5];
    const float* dw_w    = (const float*)d_in[6];
    const float* dw_b    = (const float*)d_in[7];
    const float* pw_w    = (const float*)d_in[8];
    const float* pw_b    = (const float*)d_in[9];
    const float* fuse_w  = (const float*)d_in[10];
    const float* fuse_b  = (const float*)d_in[11];

    float* attn_out = (float*)d_out;
    float* out_out  = (float*)d_out + ATTN_ELEMS;

    // 1. weight prep
    prep_kernel<<<216, 256>>>(ra_w1, ra_w2, ra_b2, fuse_w);

    // 2. fused attn-conv + softmax + einsum
    const int smem = (64 * 256 + 2 * 2048 + 200) * (int)sizeof(float); // 82720
    cudaFuncSetAttribute(attn_kernel, cudaFuncAttributeMaxDynamicSharedMemorySize, smem);
    attn_kernel<<<256, 256, smem>>>(reused, refined, attn_out);

    // 3. depthwise + relu + pointwise + residual (merged)
    dwpw_kernel<<<dim3(8, 8, 4), 256>>>(dw_w, dw_b, pw_w, pw_b);

    // 4. fuse conv + gate (o-split layout)
    fuse_kernel<<<dim3(8, 16, 4), 256>>>(hp, fuse_b, out_out);
}

// round 11
// speedup vs baseline: 1.2450x; 1.1571x over previous
#include <cuda_runtime.h>
#include <cstdint>
#include <cstddef>

// ---------------------------------------------------------------------------
// MSReversibleRefine: B=4, DIM=64, HP=32, NHEAD=8, WS=16, H=W=128
//   d_in: 0 reused_attn (256,8,256,256) | 1 refined_lms (4,64,128,128)
//         2 hp_in (4,32,128,128) | 3 ra_w1 (8,8,1,3) | 4 ra_w2 (8,8,1,1)
//         5 ra_b2 (8) | 6 dw_w (64,1,3,3) | 7 dw_b (64) | 8 pw_w (64,64,1,1)
//         9 pw_b (64) | 10 fuse_w (64,96,3,3) | 11 fuse_b (64)
//   d_out: attn (134217728 f32) ++ out (4194304 f32)
// ---------------------------------------------------------------------------
#define ATTN_ELEMS 134217728LL
#define FULLM 0xffffffffu

typedef unsigned long long ull;

// f32x2 packed helpers (SASS FFMA2 — only reachable via PTX)
__device__ __forceinline__ ull pk2(float lo, float hi) {
    ull r; asm("mov.b64 %0, {%1, %2};" : "=l"(r) : "f"(lo), "f"(hi)); return r;
}
__device__ __forceinline__ void upk2(float& lo, float& hi, ull v) {
    asm("mov.b64 {%0, %1}, %2;" : "=f"(lo), "=f"(hi) : "l"(v));
}
__device__ __forceinline__ ull fma2(ull a, ull b, ull c) {
    ull d; asm("fma.rn.f32x2 %0, %1, %2, %3;" : "=l"(d) : "l"(a), "l"(b), "l"(c)); return d;
}

// scratch (static device globals: the sanctioned no-alloc workaround)
__device__ __align__(128) float g_refl[4 * 64 * 128 * 128]; // reflashed
__device__ __align__(128) float g_res [4 * 64 * 128 * 128]; // pw + reflashed
__device__ __align__(128) float g_fw  [96 * 9 * 64];        // fuse w: [c][tap][o]
__device__ __align__(128) float g_eff [200];                // [h][24 coeffs + bias]

// ---------------------------------------------------------------------------
// prep: eff[h][ci][dx] = sum_co w2[h,co]*w1[co,ci,dx]; transpose fuse weights
// ---------------------------------------------------------------------------
__global__ void prep_kernel(const float* __restrict__ w1, const float* __restrict__ w2,
                            const float* __restrict__ b2, const float* __restrict__ fw)
{
    int t = blockIdx.x * 256 + threadIdx.x;
    if (t < 200) {
        int h = t / 25, k = t % 25;
        if (k < 24) {
            int ci = k / 3, dx = k % 3;
            float s = 0.f;
            #pragma unroll
            for (int co = 0; co < 8; co++)
                s += w2[h * 8 + co] * w1[(co * 8 + ci) * 3 + dx];
            g_eff[h * 25 + k] = s;
        } else {
            g_eff[h * 25 + 24] = b2[h];
        }
    }
    if (t < 96 * 9 * 64) {
        int o = t & 63;
        int r = t >> 6;
        int tap = r % 9;
        int c = r / 9;
        g_fw[t] = fw[(o * 96 + c) * 9 + tap];
    }
}

// ---------------------------------------------------------------------------
// attn kernel (scalar stencil): one block per window (256 blocks), warp = head.
// eff-conv -> relu -> warp softmax -> STG attn, + fused einsum in registers.
// ---------------------------------------------------------------------------
__global__ __launch_bounds__(256, 2)
void attn_kernel(const float* __restrict__ reused,
                 const float* __restrict__ refined,
                 float* __restrict__ attn_out)
{
    extern __shared__ float sm[];
    float* xw  = sm;                       // 64*256 window pixels [ch][m]
    float* buf = sm + 64 * 256;            // 2 * 8 * 256 row double buffer
    float* eff = sm + 64 * 256 + 2 * 2048; // 200

    const int bw   = blockIdx.x;
    const int tid  = threadIdx.x;
    const int h    = tid >> 5;
    const int lane = tid & 31;

    const int b  = bw >> 6;
    const int g1 = (bw >> 3) & 7;
    const int g2 = bw & 7;

    for (int i = tid; i < 200; i += 256) eff[i] = g_eff[i];

    // load window pixels: xw[ch*256 + m] = refined[b, ch, (m>>4)*8+g1, (m&15)*8+g2]
    {
        const float* rbase = refined + (size_t)b * 64 * 16384;
        for (int i = tid; i < 16384; i += 256) {
            int ch = i >> 8, m = i & 255;
            int y = ((m >> 4) << 3) + g1;
            int x = ((m & 15) << 3) + g2;
            xw[i] = rbase[ch * 16384 + y * 128 + x];
        }
    }

    float acc[8][8];
    #pragma unroll
    for (int d = 0; d < 8; d++)
        #pragma unroll
        for (int i = 0; i < 8; i++) acc[d][i] = 0.f;

    const size_t rowbase = (size_t)(bw * 8 + h) * 65536; // + m*256 per row

    // preload row m=0 (warp h loads channel h)
    {
        const float4* rl = (const float4*)(reused + rowbase);
        float4 la = __ldg(rl + lane);
        float4 lb = __ldg(rl + 32 + lane);
        float4* bp = (float4*)(buf + h * 256);
        int c0 = lane,      s0 = c0 ^ ((c0 >> 3) & 7);
        int c1 = 32 + lane, s1 = c1 ^ ((c1 >> 3) & 7);
        bp[s0] = la;
        bp[s1] = lb;
    }
    __syncthreads();

    const float bias = eff[h * 25 + 24];
    const int cA = 2 * lane;
    const int cB = cA + 1;
    const int sA = cA ^ ((cA >> 3) & 7);
    const int sB = cB ^ ((cB >> 3) & 7);

    #pragma unroll 1
    for (int m = 0; m < 256; m++) {
        const int ph = m & 1;
        const bool pre = (m + 1 < 256);
        float4 la, lb;
        if (pre) {
            const float4* rl = (const float4*)(reused + rowbase + (size_t)(m + 1) * 256);
            la = __ldg(rl + lane);
            lb = __ldg(rl + 32 + lane);
        }

        // effective 8x8x3 stencil
        float a[8];
        #pragma unroll
        for (int i = 0; i < 8; i++) a[i] = bias;

        const float4* rp = (const float4*)(buf + ph * 2048);
        #pragma unroll
        for (int c = 0; c < 8; c++) {
            float4 va = rp[c * 64 + sA];
            float4 vb = rp[c * 64 + sB];
            float v[8] = {va.x, va.y, va.z, va.w, vb.x, vb.y, vb.z, vb.w};
            float lh = __shfl_up_sync(FULLM, v[7], 1);
            float rh = __shfl_down_sync(FULLM, v[0], 1);
            if (lane == 0)  lh = 0.f;
            if (lane == 31) rh = 0.f;
            float e0 = eff[h * 25 + c * 3 + 0];
            float e1 = eff[h * 25 + c * 3 + 1];
            float e2 = eff[h * 25 + c * 3 + 2];
            #pragma unroll
            for (int i = 0; i < 8; i++) {
                float L = (i == 0) ? lh : v[i - 1];
                float R = (i == 7) ? rh : v[i + 1];
                a[i] = fmaf(e0, L, a[i]);
                a[i] = fmaf(e1, v[i], a[i]);
                a[i] = fmaf(e2, R, a[i]);
            }
        }

        // relu + warp softmax over 256 (8 per lane)
        float mx = 0.f;
        #pragma unroll
        for (int i = 0; i < 8; i++) { a[i] = fmaxf(a[i], 0.f); mx = fmaxf(mx, a[i]); }
        #pragma unroll
        for (int o = 16; o; o >>= 1) mx = fmaxf(mx, __shfl_xor_sync(FULLM, mx, o));
        float sum = 0.f;
        #pragma unroll
        for (int i = 0; i < 8; i++) { a[i] = __expf(a[i] - mx); sum += a[i]; }
        #pragma unroll
        for (int o = 16; o; o >>= 1) sum += __shfl_xor_sync(FULLM, sum, o);
        float inv = __fdividef(1.f, sum);
        #pragma unroll
        for (int i = 0; i < 8; i++) a[i] *= inv;

        // store attn row (two STG.128 per lane, warp-coalesced)
        {
            float4* op = (float4*)(attn_out + rowbase + (size_t)m * 256);
            op[2 * lane]     = make_float4(a[0], a[1], a[2], a[3]);
            op[2 * lane + 1] = make_float4(a[4], a[5], a[6], a[7]);
        }

        // fused einsum accumulate: acc[d][i] += a[i] * x[h,d,m]
        {
            const float* xcol = xw + (h * 8) * 256 + m;
            #pragma unroll
            for (int d = 0; d < 8; d++) {
                float xv = xcol[d * 256]; // broadcast LDS
                #pragma unroll
                for (int i = 0; i < 8; i++) acc[d][i] = fmaf(a[i], xv, acc[d][i]);
            }
        }

        // stage prefetched row
        if (pre) {
            float4* bp = (float4*)(buf + (ph ^ 1) * 2048 + h * 256);
            int c0 = lane,      s0 = c0 ^ ((c0 >> 3) & 7);
            int c1 = 32 + lane, s1 = c1 ^ ((c1 >> 3) & 7);
            bp[s0] = la;
            bp[s1] = lb;
        }
        __syncthreads();
    }

    // scatter reflashed: g_refl[b, h*8+d, (n>>4)*8+g1, (n&15)*8+g2]
    {
        float* gout = g_refl + ((size_t)b * 64 + h * 8) * 16384;
        #pragma unroll
        for (int d = 0; d < 8; d++) {
            #pragma unroll
            for (int i = 0; i < 8; i++) {
                int n = lane * 8 + i;
                int y = ((n >> 4) << 3) + g1;
                int x = ((n & 15) << 3) + g2;
                gout[d * 16384 + y * 128 + x] = acc[d][i];
            }
        }
    }
}

// ---------------------------------------------------------------------------
// merged depthwise 3x3 + relu + pointwise 64->64 + residual : g_refl -> g_res
// ---------------------------------------------------------------------------
__global__ __launch_bounds__(256, 2)
void dwpw_kernel(const float* __restrict__ dww, const float* __restrict__ dwb,
                 const float* __restrict__ pww, const float* __restrict__ pwb)
{
    __shared__ float tile[8 * 324];   // 8 ch x 18x18
    __shared__ float pwsh[4096];
    __shared__ float pwbsh[64];
    __shared__ float dwsh[576];
    __shared__ float dwbsh[64];

    int b   = blockIdx.z;
    int tyb = blockIdx.y * 16;
    int txb = blockIdx.x * 16;
    int tid = threadIdx.x;
    int tx  = tid & 15, ty = tid >> 4;

    for (int i = tid; i < 4096; i += 256) pwsh[i] = pww[i];
    for (int i = tid; i < 576;  i += 256) dwsh[i] = dww[i];
    if (tid < 64) { pwbsh[tid] = pwb[tid]; dwbsh[tid] = dwb[tid]; }

    ull dwp[32];

    for (int cc = 0; cc < 64; cc += 8) {
        __syncthreads();
        for (int i = tid; i < 8 * 324; i += 256) {
            int c = i / 324, r = i % 324;
            int iy = r / 18, ix = r % 18;
            int y = tyb + iy - 1, x = txb + ix - 1;
            float v = 0.f;
            if ((unsigned)y < 128u && (unsigned)x < 128u)
                v = g_refl[((size_t)b * 64 + cc + c) * 16384 + y * 128 + x];
            tile[i] = v;
        }
        __syncthreads();

        float sv[8];
        #pragma unroll
        for (int c = 0; c < 8; c++) {
            const float* w = dwsh + (cc + c) * 9;
            float s = dwbsh[cc + c];
            #pragma unroll
            for (int tap = 0; tap < 9; tap++) {
                int dy = tap / 3, dx = tap % 3;
                s = fmaf(w[tap], tile[c * 324 + (ty + dy) * 18 + (tx + dx)], s);
            }
            sv[c] = fmaxf(s, 0.f);
        }
        #pragma unroll
        for (int j = 0; j < 4; j++)
            dwp[(cc >> 1) + j] = pk2(sv[2 * j], sv[2 * j + 1]);
    }

    int y = tyb + ty, x = txb + tx;
    size_t pix = (size_t)y * 128 + x;
    const float* rin = g_refl + (size_t)b * 64 * 16384 + pix;
    float*       ro  = g_res  + (size_t)b * 64 * 16384 + pix;

    #pragma unroll 4
    for (int o = 0; o < 64; o++) {
        ull acc2 = 0ull;
        const ulonglong2* wr = (const ulonglong2*)(pwsh + o * 64);
        #pragma unroll
        for (int c4 = 0; c4 < 16; c4++) {
            ulonglong2 uw = wr[c4];
            acc2 = fma2(uw.x, dwp[2 * c4],     acc2);
            acc2 = fma2(uw.y, dwp[2 * c4 + 1], acc2);
        }
        float lo, hi;
        upk2(lo, hi, acc2);
        ro[o * 16384] = lo + hi + pwbsh[o] + rin[o * 16384];
    }
}

// ---------------------------------------------------------------------------
// fuse conv 3x3 (96 -> 64) + bias, then out = g_refl * conv.
// Layout: lane <-> o-pair (o = 2*lane, 2*lane+1), weights in registers
// (coalesced LDG.64 per lane), v warp-uniform broadcast LDS.64 from a
// DUPLICATED (v,v) tile. Per (c,tap,pixel): 1 LDS.64 (1 wavefront) +
// 1 FFMA2 (2 FMA-pipe cyc) -> FMA pipe saturated, LSU at 50%.
// Block = 128 threads = 4 warps; warp w owns pixel rows {2w, 2w+1} x 16.
// ---------------------------------------------------------------------------
__global__ __launch_bounds__(128)
void fuse_kernel(const float* __restrict__ hp, const float* __restrict__ fb,
                 float* __restrict__ out)
{
    __shared__ ull   tileu[8 * 180];      // 8 ch x 10x18, each elem = (v,v)  11520 B
    __shared__ float sacc[128 * 66];      // transpose buffer, pad 66         33792 B

    const int b   = blockIdx.z;
    const int tyb = blockIdx.y * 8;
    const int txb = blockIdx.x * 16;
    const int tid = threadIdx.x;
    const int w   = tid >> 5;             // warp 0..3
    const int lane = tid & 31;

    ull acc[32];
    #pragma unroll
    for (int p = 0; p < 32; p++) acc[p] = 0ull;

    const ull* wbase = (const ull*)g_fw;  // pair index = (c*9+tap)*32 + lane

    #pragma unroll 1
    for (int cc = 0; cc < 96; cc += 8) {
        __syncthreads();
        // stage 8-channel 10x18 duplicated tile with zero-pad halo
        for (int i = tid; i < 8 * 180; i += 128) {
            int c = i / 180, r = i % 180;
            int iy = r / 18, ix = r % 18;
            int y = tyb + iy - 1, x = txb + ix - 1;
            float v = 0.f;
            if ((unsigned)y < 128u && (unsigned)x < 128u) {
                int ch = cc + c;
                v = (ch < 64)
                    ? g_res[((size_t)b * 64 + ch) * 16384 + y * 128 + x]
                    : hp  [((size_t)b * 32 + (ch - 64)) * 16384 + y * 128 + x];
            }
            tileu[i] = pk2(v, v);
        }
        __syncthreads();

        #pragma unroll 1
        for (int c = 0; c < 8; c++) {
            // weights for this channel into registers (lane-coalesced LDG.64)
            ull wreg[9];
            const int cg = cc + c;
            #pragma unroll
            for (int tap = 0; tap < 9; tap++)
                wreg[tap] = __ldg(wbase + (cg * 9 + tap) * 32 + lane);

            // warp-uniform base for this channel + warp's row strip
            const ull* tp = tileu + c * 180 + (2 * w) * 18;
            #pragma unroll
            for (int p = 0; p < 32; p++) {
                const ull* pp = tp + (p >> 4) * 18 + (p & 15);
                #pragma unroll
                for (int tap = 0; tap < 9; tap++) {
                    ull v2 = pp[(tap / 3) * 18 + (tap % 3)]; // broadcast LDS.64
                    acc[p] = fma2(wreg[tap], v2, acc[p]);
                }
            }
        }
    }

    // transpose through padded smem, then coalesced gated store
    __syncthreads();
    #pragma unroll
    for (int p = 0; p < 32; p++) {
        float lo, hi;
        upk2(lo, hi, acc[p]);
        float* sp = sacc + (w * 32 + p) * 66 + 2 * lane;
        sp[0] = lo;
        sp[1] = hi;
    }
    __syncthreads();

    for (int i = tid; i < 8192; i += 128) {
        int px = i & 15;
        int o  = (i >> 4) & 63;
        int py = i >> 10;
        int p  = (py >> 1) * 32 + (py & 1) * 16 + px;
        float v = sacc[p * 66 + o] + fb[o];
        size_t idx = ((size_t)b * 64 + o) * 16384 + (size_t)(tyb + py) * 128 + (txb + px);
        out[idx] = g_refl[idx] * v;
    }
}

// ---------------------------------------------------------------------------
extern "C" void kernel_launch(void* const* d_in, const int* in_sizes, int n_in,
                              void* d_out, int out_size)
{
    const float* reused  = (const float*)d_in[0];
    const float* refined = (const float*)d_in[1];
    const float* hp      = (const float*)d_in[2];
    const float* ra_w1   = (const float*)d_in[3];
    const float* ra_w2   = (const float*)d_in[4];
    const float* ra_b2   = (const float*)d_in[5];
    const float* dw_w    = (const float*)d_in[6];
    const float* dw_b    = (const float*)d_in[7];
    const float* pw_w    = (const float*)d_in[8];
    const float* pw_b    = (const float*)d_in[9];
    const float* fuse_w  = (const float*)d_in[10];
    const float* fuse_b  = (const float*)d_in[11];

    float* attn_out = (float*)d_out;
    float* out_out  = (float*)d_out + ATTN_ELEMS;

    // 1. weight prep
    prep_kernel<<<216, 256>>>(ra_w1, ra_w2, ra_b2, fuse_w);

    // 2. fused attn-conv + softmax + einsum
    const int smem = (64 * 256 + 2 * 2048 + 200) * (int)sizeof(float); // 82720
    cudaFuncSetAttribute(attn_kernel, cudaFuncAttributeMaxDynamicSharedMemorySize, smem);
    attn_kernel<<<256, 256, smem>>>(reused, refined, attn_out);

    // 3. depthwise + relu + pointwise + residual (merged)
    dwpw_kernel<<<dim3(8, 8, 4), 256>>>(dw_w, dw_b, pw_w, pw_b);

    // 4. fuse conv + gate (register-weight layout)
    fuse_kernel<<<dim3(8, 16, 4), 128>>>(hp, fuse_b, out_out);
}